// round 1
// baseline (speedup 1.0000x reference)
#include <cuda_runtime.h>

#define H   2048
#define I   1408
#define E   8
#define T   512
#define I2  2816   // 2*I

typedef unsigned long long ull;

// ---------------- device scratch (no allocations allowed) ----------------
__device__ int   g_cnt[E];
__device__ int   g_tok[E][T];
__device__ float g_cw [E][T];
__device__ float g_act[(size_t)E * T * I];   // ~23 MB, rows >= cnt stay zero

// ---------------- packed f32x2 helpers ----------------
__device__ __forceinline__ void fma2(ull& d, ull a, ull b) {
    asm("fma.rn.f32x2 %0, %1, %2, %0;" : "+l"(d) : "l"(a), "l"(b));
}
__device__ __forceinline__ float2 unpack2(ull v) {
    float2 f;
    asm("mov.b64 {%0, %1}, %2;" : "=f"(f.x), "=f"(f.y) : "l"(v));
    return f;
}

// ---------------- reset: zero output + expert counters ----------------
__global__ void k_reset(float* __restrict__ out) {
    int idx = blockIdx.x * blockDim.x + threadIdx.x;
    if (idx < T * H) out[idx] = 0.f;
    if (idx < E) g_cnt[idx] = 0;
}

// ---------------- router: softmax -> top2 -> renorm -> expert lists ----------------
__global__ void k_router(const float* __restrict__ x, const float* __restrict__ wg) {
    const int t    = blockIdx.x;
    const int tid  = threadIdx.x;       // 256 threads = 8 warps
    const int w    = tid >> 5;
    const int lane = tid & 31;

    const float* xr = x  + (size_t)t * H;
    const float* gr = wg + (size_t)w * H;
    float s = 0.f;
    for (int i = lane * 4; i < H; i += 128) {
        float4 xv = *(const float4*)(xr + i);
        float4 gv = *(const float4*)(gr + i);
        s += xv.x * gv.x + xv.y * gv.y + xv.z * gv.z + xv.w * gv.w;
    }
    #pragma unroll
    for (int o = 16; o; o >>= 1) s += __shfl_xor_sync(0xffffffffu, s, o);

    __shared__ float lg[E];
    if (lane == 0) lg[w] = s;
    __syncthreads();

    if (tid == 0) {
        float mx = lg[0];
        #pragma unroll
        for (int e = 1; e < E; e++) mx = fmaxf(mx, lg[e]);
        float ex[E];
        #pragma unroll
        for (int e = 0; e < E; e++) ex[e] = expf(lg[e] - mx);
        // top-2 (lowest index wins ties, matching jax top_k)
        int i0 = 0;
        #pragma unroll
        for (int e = 1; e < E; e++) if (ex[e] > ex[i0]) i0 = e;
        int i1 = (i0 == 0) ? 1 : 0;
        #pragma unroll
        for (int e = 0; e < E; e++) if (e != i0 && ex[e] > ex[i1]) i1 = e;
        // softmax denominator cancels in the top-k renormalization
        float s0 = ex[i0], s1 = ex[i1];
        float inv = 1.f / (s0 + s1);
        int p0 = atomicAdd(&g_cnt[i0], 1);
        g_tok[i0][p0] = t;  g_cw[i0][p0] = s0 * inv;
        int p1 = atomicAdd(&g_cnt[i1], 1);
        g_tok[i1][p1] = t;  g_cw[i1][p1] = s1 * inv;
    }
}

// ---------------- GEMM1: act = silu(x @ Wg^T) * (x @ Wu^T) per expert ----------------
// BM=64, BN=64 (of I), BK=16, 256 threads, 4x4 microtile, f32x2 FMA.
__global__ void __launch_bounds__(256) k_gemm1(const float* __restrict__ x,
                                               const float* __restrict__ w1) {
    const int e   = blockIdx.z;
    const int cnt = g_cnt[e];
    const int m0  = blockIdx.y * 64;
    if (m0 >= cnt) return;
    const int n0  = blockIdx.x * 64;

    __shared__ float As[16][64];
    __shared__ float Gd[16][128];   // gate rows duplicated (b,b)
    __shared__ float Ud[16][128];   // up   rows duplicated (b,b)

    const int tid = threadIdx.x;
    const int lr  = tid >> 2;          // 0..63 tile row for loads
    const int lk  = (tid & 3) << 2;    // 0,4,8,12 k offset for loads
    const int ty  = tid >> 4;          // 0..15
    const int tx  = tid & 15;          // 0..15

    const int arow = m0 + lr;
    const int tok  = g_tok[e][arow < cnt ? arow : (cnt - 1)];
    const float* aptr = x  + (size_t)tok * H + lk;
    const float* gptr = w1 + ((size_t)e * I2 + (n0 + lr)) * H + lk;
    const float* uptr = w1 + ((size_t)e * I2 + I + (n0 + lr)) * H + lk;

    ull accg[2][4] = {}, accu[2][4] = {};

    for (int k0 = 0; k0 < H; k0 += 16) {
        float4 a = *(const float4*)(aptr + k0);
        float4 g = *(const float4*)(gptr + k0);
        float4 u = *(const float4*)(uptr + k0);
        __syncthreads();
        As[lk + 0][lr] = a.x;  As[lk + 1][lr] = a.y;
        As[lk + 2][lr] = a.z;  As[lk + 3][lr] = a.w;
        *(float2*)&Gd[lk + 0][2 * lr] = make_float2(g.x, g.x);
        *(float2*)&Gd[lk + 1][2 * lr] = make_float2(g.y, g.y);
        *(float2*)&Gd[lk + 2][2 * lr] = make_float2(g.z, g.z);
        *(float2*)&Gd[lk + 3][2 * lr] = make_float2(g.w, g.w);
        *(float2*)&Ud[lk + 0][2 * lr] = make_float2(u.x, u.x);
        *(float2*)&Ud[lk + 1][2 * lr] = make_float2(u.y, u.y);
        *(float2*)&Ud[lk + 2][2 * lr] = make_float2(u.z, u.z);
        *(float2*)&Ud[lk + 3][2 * lr] = make_float2(u.w, u.w);
        __syncthreads();

        #pragma unroll
        for (int kk = 0; kk < 16; kk++) {
            ull a01 = *(const ull*)&As[kk][ty << 2];
            ull a23 = *(const ull*)&As[kk][(ty << 2) + 2];
            const ull* gp = (const ull*)&Gd[kk][tx << 3];
            const ull* up = (const ull*)&Ud[kk][tx << 3];
            #pragma unroll
            for (int j = 0; j < 4; j++) {
                fma2(accg[0][j], a01, gp[j]);
                fma2(accg[1][j], a23, gp[j]);
                fma2(accu[0][j], a01, up[j]);
                fma2(accu[1][j], a23, up[j]);
            }
        }
    }

    #pragma unroll
    for (int ip = 0; ip < 2; ip++) {
        #pragma unroll
        for (int hh = 0; hh < 2; hh++) {
            const int m = m0 + (ty << 2) + ip * 2 + hh;
            if (m >= cnt) continue;
            float* orow = g_act + ((size_t)e * T + m) * I + n0 + (tx << 2);
            #pragma unroll
            for (int j = 0; j < 4; j++) {
                float2 gg = unpack2(accg[ip][j]);
                float2 uu = unpack2(accu[ip][j]);
                float gv = hh ? gg.y : gg.x;
                float uv = hh ? uu.y : uu.x;
                orow[j] = gv / (1.f + __expf(-gv)) * uv;   // silu(g) * u
            }
        }
    }
}

// ---------------- GEMM2: out[tok] += cw * (act @ W2^T) per expert ----------------
__global__ void __launch_bounds__(256) k_gemm2(const float* __restrict__ w2,
                                               float* __restrict__ out) {
    const int e   = blockIdx.z;
    const int cnt = g_cnt[e];
    const int m0  = blockIdx.y * 64;
    if (m0 >= cnt) return;
    const int n0  = blockIdx.x * 64;

    __shared__ float As[16][64];
    __shared__ float Bd[16][128];

    const int tid = threadIdx.x;
    const int lr  = tid >> 2;
    const int lk  = (tid & 3) << 2;
    const int ty  = tid >> 4;
    const int tx  = tid & 15;

    const float* aptr = g_act + ((size_t)e * T + (m0 + lr)) * I + lk;
    const float* bptr = w2 + ((size_t)e * H + (n0 + lr)) * I + lk;

    ull acc[2][4] = {};

    for (int k0 = 0; k0 < I; k0 += 16) {
        float4 a = *(const float4*)(aptr + k0);
        float4 b = *(const float4*)(bptr + k0);
        __syncthreads();
        As[lk + 0][lr] = a.x;  As[lk + 1][lr] = a.y;
        As[lk + 2][lr] = a.z;  As[lk + 3][lr] = a.w;
        *(float2*)&Bd[lk + 0][2 * lr] = make_float2(b.x, b.x);
        *(float2*)&Bd[lk + 1][2 * lr] = make_float2(b.y, b.y);
        *(float2*)&Bd[lk + 2][2 * lr] = make_float2(b.z, b.z);
        *(float2*)&Bd[lk + 3][2 * lr] = make_float2(b.w, b.w);
        __syncthreads();

        #pragma unroll
        for (int kk = 0; kk < 16; kk++) {
            ull a01 = *(const ull*)&As[kk][ty << 2];
            ull a23 = *(const ull*)&As[kk][(ty << 2) + 2];
            const ull* bp = (const ull*)&Bd[kk][tx << 3];
            #pragma unroll
            for (int j = 0; j < 4; j++) {
                fma2(acc[0][j], a01, bp[j]);
                fma2(acc[1][j], a23, bp[j]);
            }
        }
    }

    #pragma unroll
    for (int ip = 0; ip < 2; ip++) {
        #pragma unroll
        for (int hh = 0; hh < 2; hh++) {
            const int m = m0 + (ty << 2) + ip * 2 + hh;
            if (m >= cnt) continue;
            const int   tok = g_tok[e][m];
            const float cw  = g_cw[e][m];
            float* op = out + (size_t)tok * H + n0 + (tx << 2);
            #pragma unroll
            for (int j = 0; j < 4; j++) {
                float2 v = unpack2(acc[ip][j]);
                atomicAdd(op + j, (hh ? v.y : v.x) * cw);
            }
        }
    }
}

// ---------------- launch ----------------
extern "C" void kernel_launch(void* const* d_in, const int* in_sizes, int n_in,
                              void* d_out, int out_size) {
    const float* x  = (const float*)d_in[0];   // [T, H]
    const float* w1 = (const float*)d_in[1];   // [E, 2I, H]
    const float* w2 = (const float*)d_in[2];   // [E, H, I]
    const float* wg = (const float*)d_in[3];   // [E, H]
    float* out = (float*)d_out;                // [T, 1, H]

    k_reset<<<(T * H + 255) / 256, 256>>>(out);
    k_router<<<T, 256>>>(x, wg);
    k_gemm1<<<dim3(I / 64, (T + 63) / 64, E), 256>>>(x, w1);
    k_gemm2<<<dim3(H / 64, (T + 63) / 64, E), 256>>>(w2, out);
}

// round 2
// speedup vs baseline: 2.5871x; 2.5871x over previous
#include <cuda_runtime.h>

#define H   2048
#define I   1408
#define E   8
#define T   512
#define I2  2816   // 2*I

typedef unsigned long long ull;

// ---------------- device scratch (no allocations allowed) ----------------
__device__ int   g_cnt[E];
__device__ int   g_tok[E][T];
__device__ float g_cw [E][T];
__device__ float g_act[(size_t)E * T * I];   // ~23 MB

// ---------------- packed f32x2 helpers ----------------
__device__ __forceinline__ void fma2(ull& d, ull a, ull b) {
    asm("fma.rn.f32x2 %0, %1, %2, %0;" : "+l"(d) : "l"(a), "l"(b));
}
__device__ __forceinline__ ull dup2(float v) {
    ull r;
    asm("mov.b64 %0, {%1, %1};" : "=l"(r) : "f"(v));
    return r;
}
__device__ __forceinline__ float2 unpack2(ull v) {
    float2 f;
    asm("mov.b64 {%0, %1}, %2;" : "=f"(f.x), "=f"(f.y) : "l"(v));
    return f;
}

// ---------------- reset: zero output + expert counters ----------------
__global__ void k_reset(float* __restrict__ out) {
    int idx = blockIdx.x * blockDim.x + threadIdx.x;
    if (idx < T * H) out[idx] = 0.f;
    if (idx < E) g_cnt[idx] = 0;
}

// ---------------- router: softmax -> top2 -> renorm -> expert lists ----------------
__global__ void k_router(const float* __restrict__ x, const float* __restrict__ wg) {
    const int t    = blockIdx.x;
    const int tid  = threadIdx.x;       // 256 threads = 8 warps
    const int w    = tid >> 5;
    const int lane = tid & 31;

    const float* xr = x  + (size_t)t * H;
    const float* gr = wg + (size_t)w * H;
    float s = 0.f;
    for (int i = lane * 4; i < H; i += 128) {
        float4 xv = *(const float4*)(xr + i);
        float4 gv = *(const float4*)(gr + i);
        s += xv.x * gv.x + xv.y * gv.y + xv.z * gv.z + xv.w * gv.w;
    }
    #pragma unroll
    for (int o = 16; o; o >>= 1) s += __shfl_xor_sync(0xffffffffu, s, o);

    __shared__ float lg[E];
    if (lane == 0) lg[w] = s;
    __syncthreads();

    if (tid == 0) {
        float mx = lg[0];
        #pragma unroll
        for (int e = 1; e < E; e++) mx = fmaxf(mx, lg[e]);
        float ex[E];
        #pragma unroll
        for (int e = 0; e < E; e++) ex[e] = expf(lg[e] - mx);
        int i0 = 0;
        #pragma unroll
        for (int e = 1; e < E; e++) if (ex[e] > ex[i0]) i0 = e;
        int i1 = (i0 == 0) ? 1 : 0;
        #pragma unroll
        for (int e = 0; e < E; e++) if (e != i0 && ex[e] > ex[i1]) i1 = e;
        float s0 = ex[i0], s1 = ex[i1];
        float inv = 1.f / (s0 + s1);
        int p0 = atomicAdd(&g_cnt[i0], 1);
        g_tok[i0][p0] = t;  g_cw[i0][p0] = s0 * inv;
        int p1 = atomicAdd(&g_cnt[i1], 1);
        g_tok[i1][p1] = t;  g_cw[i1][p1] = s1 * inv;
    }
}

// ---------------- GEMM1: act = silu(x@Wg^T) * (x@Wu^T), BM=128 BN=64 BK=16 ----------------
// 256 threads: ty=tid>>4 (8 m rows each), tx=tid&15 (4 n cols each, gate+up).
__global__ void __launch_bounds__(256) k_gemm1(const float* __restrict__ x,
                                               const float* __restrict__ w1) {
    const int e   = blockIdx.z;
    const int cnt = g_cnt[e];
    const int m0  = blockIdx.y * 128;
    if (m0 >= cnt) return;
    const int n0  = blockIdx.x * 64;

    __shared__ float As[16][128];
    __shared__ float Gs[16][64];
    __shared__ float Us[16][64];

    const int tid = threadIdx.x;
    // A loader: 128 rows x 16 k, 2 float4 per thread
    const int alm = tid & 127;
    const int alk = (tid >> 7) * 4;          // 0 or 4; second quad at +8
    int arow = m0 + alm; if (arow >= cnt) arow = cnt - 1;
    const float* aptr = x + (size_t)g_tok[e][arow] * H + alk;
    // B loaders: 64 rows x 16 k each, 1 float4 per thread
    const int blr = tid & 63;
    const int blk = (tid >> 6) * 4;          // 0,4,8,12
    const float* gptr = w1 + ((size_t)e * I2 + n0 + blr) * H + blk;
    const float* uptr = gptr + (size_t)I * H;

    const int ty = tid >> 4;
    const int tx = tid & 15;

    ull ag[8][2] = {}, au[8][2] = {};

    float4 a0 = *(const float4*)(aptr);
    float4 a1 = *(const float4*)(aptr + 8);
    float4 gv = *(const float4*)(gptr);
    float4 uv = *(const float4*)(uptr);

    for (int k0 = 0; k0 < H; k0 += 16) {
        __syncthreads();
        As[alk + 0][alm] = a0.x;  As[alk + 1][alm] = a0.y;
        As[alk + 2][alm] = a0.z;  As[alk + 3][alm] = a0.w;
        As[alk + 8][alm] = a1.x;  As[alk + 9][alm] = a1.y;
        As[alk +10][alm] = a1.z;  As[alk +11][alm] = a1.w;
        Gs[blk + 0][blr] = gv.x;  Gs[blk + 1][blr] = gv.y;
        Gs[blk + 2][blr] = gv.z;  Gs[blk + 3][blr] = gv.w;
        Us[blk + 0][blr] = uv.x;  Us[blk + 1][blr] = uv.y;
        Us[blk + 2][blr] = uv.z;  Us[blk + 3][blr] = uv.w;
        __syncthreads();
        if (k0 + 16 < H) {
            a0 = *(const float4*)(aptr + k0 + 16);
            a1 = *(const float4*)(aptr + k0 + 24);
            gv = *(const float4*)(gptr + k0 + 16);
            uv = *(const float4*)(uptr + k0 + 16);
        }
        #pragma unroll
        for (int kk = 0; kk < 16; kk++) {
            const float* ar = &As[kk][ty * 8];
            float4 av0 = *(const float4*)ar;
            float4 av1 = *(const float4*)(ar + 4);
            ull ap[8];
            ap[0] = dup2(av0.x); ap[1] = dup2(av0.y);
            ap[2] = dup2(av0.z); ap[3] = dup2(av0.w);
            ap[4] = dup2(av1.x); ap[5] = dup2(av1.y);
            ap[6] = dup2(av1.z); ap[7] = dup2(av1.w);
            const ull* gp = (const ull*)&Gs[kk][tx * 4];
            const ull* up = (const ull*)&Us[kk][tx * 4];
            ull g0 = gp[0], g1 = gp[1];
            ull u0 = up[0], u1 = up[1];
            #pragma unroll
            for (int m = 0; m < 8; m++) {
                fma2(ag[m][0], ap[m], g0);
                fma2(ag[m][1], ap[m], g1);
                fma2(au[m][0], ap[m], u0);
                fma2(au[m][1], ap[m], u1);
            }
        }
    }

    #pragma unroll
    for (int m = 0; m < 8; m++) {
        const int row = m0 + ty * 8 + m;
        if (row >= cnt) continue;
        float* op = g_act + ((size_t)e * T + row) * I + n0 + tx * 4;
        float2 G0 = unpack2(ag[m][0]), G1 = unpack2(ag[m][1]);
        float2 U0 = unpack2(au[m][0]), U1 = unpack2(au[m][1]);
        float4 r;
        r.x = G0.x / (1.f + __expf(-G0.x)) * U0.x;
        r.y = G0.y / (1.f + __expf(-G0.y)) * U0.y;
        r.z = G1.x / (1.f + __expf(-G1.x)) * U1.x;
        r.w = G1.y / (1.f + __expf(-G1.y)) * U1.y;
        *(float4*)op = r;
    }
}

// ---------------- GEMM2: out[tok] += cw * (act @ W2^T), BM=128 BN=128 BK=16 ----------------
__global__ void __launch_bounds__(256) k_gemm2(const float* __restrict__ w2,
                                               float* __restrict__ out) {
    const int e   = blockIdx.z;
    const int cnt = g_cnt[e];
    const int m0  = blockIdx.y * 128;
    if (m0 >= cnt) return;
    const int n0  = blockIdx.x * 128;

    __shared__ float As[16][128];
    __shared__ float Bs[16][128];

    const int tid = threadIdx.x;
    const int lm  = tid & 127;
    const int lk  = (tid >> 7) * 4;          // 0 or 4; second quad at +8
    // rows >= cnt hold stale-but-finite data; epilogue guards. m0+lm < T always.
    const float* aptr = g_act + ((size_t)e * T + m0 + lm) * I + lk;
    const float* bptr = w2 + ((size_t)e * H + n0 + lm) * I + lk;

    const int ty = tid >> 4;
    const int tx = tid & 15;

    ull acc[8][4] = {};

    float4 a0 = *(const float4*)(aptr);
    float4 a1 = *(const float4*)(aptr + 8);
    float4 b0 = *(const float4*)(bptr);
    float4 b1 = *(const float4*)(bptr + 8);

    for (int k0 = 0; k0 < I; k0 += 16) {
        __syncthreads();
        As[lk + 0][lm] = a0.x;  As[lk + 1][lm] = a0.y;
        As[lk + 2][lm] = a0.z;  As[lk + 3][lm] = a0.w;
        As[lk + 8][lm] = a1.x;  As[lk + 9][lm] = a1.y;
        As[lk +10][lm] = a1.z;  As[lk +11][lm] = a1.w;
        Bs[lk + 0][lm] = b0.x;  Bs[lk + 1][lm] = b0.y;
        Bs[lk + 2][lm] = b0.z;  Bs[lk + 3][lm] = b0.w;
        Bs[lk + 8][lm] = b1.x;  Bs[lk + 9][lm] = b1.y;
        Bs[lk +10][lm] = b1.z;  Bs[lk +11][lm] = b1.w;
        __syncthreads();
        if (k0 + 16 < I) {
            a0 = *(const float4*)(aptr + k0 + 16);
            a1 = *(const float4*)(aptr + k0 + 24);
            b0 = *(const float4*)(bptr + k0 + 16);
            b1 = *(const float4*)(bptr + k0 + 24);
        }
        #pragma unroll
        for (int kk = 0; kk < 16; kk++) {
            const float* ar = &As[kk][ty * 8];
            float4 av0 = *(const float4*)ar;
            float4 av1 = *(const float4*)(ar + 4);
            ull ap[8];
            ap[0] = dup2(av0.x); ap[1] = dup2(av0.y);
            ap[2] = dup2(av0.z); ap[3] = dup2(av0.w);
            ap[4] = dup2(av1.x); ap[5] = dup2(av1.y);
            ap[6] = dup2(av1.z); ap[7] = dup2(av1.w);
            const ull* bp = (const ull*)&Bs[kk][tx * 8];
            ull v0 = bp[0], v1 = bp[1], v2 = bp[2], v3 = bp[3];
            #pragma unroll
            for (int m = 0; m < 8; m++) {
                fma2(acc[m][0], ap[m], v0);
                fma2(acc[m][1], ap[m], v1);
                fma2(acc[m][2], ap[m], v2);
                fma2(acc[m][3], ap[m], v3);
            }
        }
    }

    #pragma unroll
    for (int m = 0; m < 8; m++) {
        const int row = m0 + ty * 8 + m;
        if (row >= cnt) continue;
        const int   tok = g_tok[e][row];
        const float cw  = g_cw[e][row];
        float* op = out + (size_t)tok * H + n0 + tx * 8;
        #pragma unroll
        for (int j = 0; j < 4; j++) {
            float2 v = unpack2(acc[m][j]);
            atomicAdd(op + 2 * j,     v.x * cw);
            atomicAdd(op + 2 * j + 1, v.y * cw);
        }
    }
}

// ---------------- launch ----------------
extern "C" void kernel_launch(void* const* d_in, const int* in_sizes, int n_in,
                              void* d_out, int out_size) {
    const float* x  = (const float*)d_in[0];   // [T, H]
    const float* w1 = (const float*)d_in[1];   // [E, 2I, H]
    const float* w2 = (const float*)d_in[2];   // [E, H, I]
    const float* wg = (const float*)d_in[3];   // [E, H]
    float* out = (float*)d_out;                // [T, 1, H]

    k_reset<<<(T * H + 255) / 256, 256>>>(out);
    k_router<<<T, 256>>>(x, wg);
    k_gemm1<<<dim3(I / 64, (T + 127) / 128, E), 256>>>(x, w1);
    k_gemm2<<<dim3(H / 128, (T + 127) / 128, E), 256>>>(w2, out);
}

// round 4
// speedup vs baseline: 5.7476x; 2.2216x over previous
#include <cuda_runtime.h>
#include <cstdint>

#define H   2048
#define I   1408
#define E   8
#define T   512
#define I2  2816   // 2*I
#define IW  (I/2)  // act row width in uint32 (bf16 pairs)

// ---------------- device scratch (no allocations allowed) ----------------
__device__ int   g_cnt[E];
__device__ int   g_tok[E][T];
__device__ float g_cw [E][T];
__device__ __align__(16) uint32_t g_act_hi[(size_t)E * T * IW];  // bf16 pairs
__device__ __align__(16) uint32_t g_act_lo[(size_t)E * T * IW];

// ---------------- helpers ----------------
__device__ __forceinline__ uint32_t smem_u32(const void* p) {
    uint32_t a;
    asm("{ .reg .u64 t; cvta.to.shared.u64 t, %1; cvt.u32.u64 %0, t; }" : "=r"(a) : "l"(p));
    return a;
}
// pack two fp32 -> bf16x2 (lo in lower 16 bits, hi in upper)
__device__ __forceinline__ uint32_t packbf(float lo, float hi) {
    uint32_t r;
    asm("cvt.rn.bf16x2.f32 %0, %1, %2;" : "=r"(r) : "f"(hi), "f"(lo));
    return r;
}
// split float4 into bf16 hi words (h0,h1) and residual lo words (l0,l1)
__device__ __forceinline__ void split4(float4 v, uint32_t& h0, uint32_t& h1,
                                       uint32_t& l0, uint32_t& l1) {
    h0 = packbf(v.x, v.y);
    h1 = packbf(v.z, v.w);
    float fx = __uint_as_float(h0 << 16), fy = __uint_as_float(h0 & 0xFFFF0000u);
    float fz = __uint_as_float(h1 << 16), fw = __uint_as_float(h1 & 0xFFFF0000u);
    l0 = packbf(v.x - fx, v.y - fy);
    l1 = packbf(v.z - fz, v.w - fw);
}
__device__ __forceinline__ void ldsm4(uint32_t* r, uint32_t a) {
    asm volatile("ldmatrix.sync.aligned.m8n8.x4.shared.b16 {%0,%1,%2,%3}, [%4];"
        : "=r"(r[0]), "=r"(r[1]), "=r"(r[2]), "=r"(r[3]) : "r"(a));
}
__device__ __forceinline__ void mma_bf(float* d, const uint32_t* a, uint32_t b0, uint32_t b1) {
    asm volatile("mma.sync.aligned.m16n8k16.row.col.f32.bf16.bf16.f32 "
        "{%0,%1,%2,%3}, {%4,%5,%6,%7}, {%8,%9}, {%0,%1,%2,%3};"
        : "+f"(d[0]), "+f"(d[1]), "+f"(d[2]), "+f"(d[3])
        : "r"(a[0]), "r"(a[1]), "r"(a[2]), "r"(a[3]), "r"(b0), "r"(b1));
}

// ---------------- reset ----------------
__global__ void k_reset(float* __restrict__ out) {
    int idx = blockIdx.x * blockDim.x + threadIdx.x;
    if (idx < T * H) out[idx] = 0.f;
    if (idx < E) g_cnt[idx] = 0;
}

// ---------------- router ----------------
__global__ void k_router(const float* __restrict__ x, const float* __restrict__ wg) {
    const int t = blockIdx.x, tid = threadIdx.x, w = tid >> 5, lane = tid & 31;
    const float* xr = x  + (size_t)t * H;
    const float* gr = wg + (size_t)w * H;
    float s = 0.f;
    for (int i = lane * 4; i < H; i += 128) {
        float4 xv = *(const float4*)(xr + i);
        float4 gv = *(const float4*)(gr + i);
        s += xv.x * gv.x + xv.y * gv.y + xv.z * gv.z + xv.w * gv.w;
    }
    #pragma unroll
    for (int o = 16; o; o >>= 1) s += __shfl_xor_sync(0xffffffffu, s, o);
    __shared__ float lg[E];
    if (lane == 0) lg[w] = s;
    __syncthreads();
    if (tid == 0) {
        float mx = lg[0];
        #pragma unroll
        for (int e = 1; e < E; e++) mx = fmaxf(mx, lg[e]);
        float ex[E];
        #pragma unroll
        for (int e = 0; e < E; e++) ex[e] = expf(lg[e] - mx);
        int i0 = 0;
        #pragma unroll
        for (int e = 1; e < E; e++) if (ex[e] > ex[i0]) i0 = e;
        int i1 = (i0 == 0) ? 1 : 0;
        #pragma unroll
        for (int e = 0; e < E; e++) if (e != i0 && ex[e] > ex[i1]) i1 = e;
        float s0 = ex[i0], s1 = ex[i1], inv = 1.f / (s0 + s1);
        int p0 = atomicAdd(&g_cnt[i0], 1);
        g_tok[i0][p0] = t;  g_cw[i0][p0] = s0 * inv;
        int p1 = atomicAdd(&g_cnt[i1], 1);
        g_tok[i1][p1] = t;  g_cw[i1][p1] = s1 * inv;
    }
}

// SMEM tile geometry: per stage 0x8000 bytes = A[128 rows][128B] + B[128][128B],
// each row: bytes [0,64) = hi bf16 (k 0..31), [64,128) = lo bf16, SW128 swizzle.
// compute macro shared by both GEMMs (stage pointers differ)
#define COMPUTE_STAGE(aoff_, boff_)                                             \
    {                                                                           \
        _Pragma("unroll")                                                       \
        for (int kk = 0; kk < 2; kk++) {                                        \
            uint32_t Ah[2][4], Al[2][4], Bh[4][4], Bl[4][4];                    \
            _Pragma("unroll")                                                   \
            for (int mt = 0; mt < 2; mt++) {                                    \
                uint32_t off = a_swb + mt * 2048;                               \
                ldsm4(Ah[mt], (aoff_) + (off ^ (kk << 5)));                     \
                ldsm4(Al[mt], (aoff_) + (off ^ (kk << 5) ^ 64));                \
            }                                                                   \
            _Pragma("unroll")                                                   \
            for (int n2 = 0; n2 < 4; n2++) {                                    \
                uint32_t off = b_swb + n2 * 2048;                               \
                ldsm4(Bh[n2], (boff_) + (off ^ (kk << 5)));                     \
                ldsm4(Bl[n2], (boff_) + (off ^ (kk << 5) ^ 64));                \
            }                                                                   \
            _Pragma("unroll")                                                   \
            for (int mt = 0; mt < 2; mt++)                                      \
                _Pragma("unroll")                                               \
                for (int n2 = 0; n2 < 4; n2++) {                                \
                    mma_bf(acc[mt][2 * n2],     Ah[mt], Bh[n2][0], Bh[n2][1]);  \
                    mma_bf(acc[mt][2 * n2 + 1], Ah[mt], Bh[n2][2], Bh[n2][3]);  \
                }                                                               \
            _Pragma("unroll")                                                   \
            for (int mt = 0; mt < 2; mt++)                                      \
                _Pragma("unroll")                                               \
                for (int n2 = 0; n2 < 4; n2++) {                                \
                    mma_bf(acc[mt][2 * n2],     Ah[mt], Bl[n2][0], Bl[n2][1]);  \
                    mma_bf(acc[mt][2 * n2 + 1], Ah[mt], Bl[n2][2], Bl[n2][3]);  \
                }                                                               \
            _Pragma("unroll")                                                   \
            for (int mt = 0; mt < 2; mt++)                                      \
                _Pragma("unroll")                                               \
                for (int n2 = 0; n2 < 4; n2++) {                                \
                    mma_bf(acc[mt][2 * n2],     Al[mt], Bh[n2][0], Bh[n2][1]);  \
                    mma_bf(acc[mt][2 * n2 + 1], Al[mt], Bh[n2][2], Bh[n2][3]);  \
                }                                                               \
        }                                                                       \
    }

// ---------------- GEMM1: act = silu(x@Wg^T)*(x@Wu^T) ----------------
// grid (I/64, 4, E); BM=128, N-tile = 64 gate rows + 64 up rows, BK=32.
__global__ void __launch_bounds__(256, 1) k_gemm1(const float* __restrict__ x,
                                                  const float* __restrict__ w1) {
    const int e = blockIdx.z, cnt = g_cnt[e];
    const int m0 = blockIdx.y * 128;
    if (m0 >= cnt) return;
    const int n0 = blockIdx.x * 64;

    extern __shared__ char sm[];
    const uint32_t sbase = smem_u32(sm);
    __shared__ int s_tok[128];

    const int tid = threadIdx.x, lane = tid & 31, wid = tid >> 5;
    if (tid < 128) { int r = m0 + tid; if (r >= cnt) r = cnt - 1; s_tok[tid] = g_tok[e][r]; }
    __syncthreads();

    // loaders: 2 threads per row, 16 consecutive floats each
    const int lrow = tid >> 1, lkq = (tid & 1) * 16;
    const float* aptr = x + (size_t)s_tok[lrow] * H + lkq;
    const int wrow = (lrow < 64) ? (n0 + lrow) : (I + n0 + lrow - 64);
    const float* bptr = w1 + ((size_t)e * I2 + wrow) * H + lkq;
    const uint32_t s_sw = (uint32_t)(lrow * 128 + lkq * 2) ^ (((uint32_t)lrow & 7) << 4);

    // compute-side fragment bases
    const int wm = (wid & 3) * 32, wn = (wid >> 2) * 64;
    const uint32_t a_row = wm + (lane & 15);
    const uint32_t a_swb = (a_row * 128 + ((lane >> 4) << 4)) ^ ((a_row & 7) << 4);
    const uint32_t b_row = wn + (lane & 7) + ((lane >> 4) << 3);
    const uint32_t b_swb = (b_row * 128 + (((lane >> 3) & 1) << 4)) ^ ((b_row & 7) << 4);

    float acc[2][8][4] = {};
    float4 av[4], bv[4];
    #pragma unroll
    for (int i = 0; i < 4; i++) { av[i] = *(const float4*)(aptr + 4 * i); bv[i] = *(const float4*)(bptr + 4 * i); }
    {   // STS stage 0
        char* sA = sm;  char* sB = sm + 0x4000;
        #pragma unroll
        for (int i = 0; i < 4; i++) {
            uint32_t h0, h1, l0, l1, o = s_sw ^ (i << 3);
            split4(av[i], h0, h1, l0, l1);
            *(uint2*)(sA + o) = make_uint2(h0, h1);
            *(uint2*)(sA + (o ^ 64)) = make_uint2(l0, l1);
            split4(bv[i], h0, h1, l0, l1);
            *(uint2*)(sB + o) = make_uint2(h0, h1);
            *(uint2*)(sB + (o ^ 64)) = make_uint2(l0, l1);
        }
    }
    __syncthreads();

    const int KT = H / 32;
    for (int kt = 0; kt < KT; kt++) {
        const int b = kt & 1;
        if (kt + 1 < KT) {
            const int k0 = (kt + 1) * 32;
            #pragma unroll
            for (int i = 0; i < 4; i++) {
                av[i] = *(const float4*)(aptr + k0 + 4 * i);
                bv[i] = *(const float4*)(bptr + k0 + 4 * i);
            }
        }
        const uint32_t aoff = sbase + b * 0x8000;
        const uint32_t boff = aoff + 0x4000;
        COMPUTE_STAGE(aoff, boff);
        if (kt + 1 < KT) {
            __syncthreads();
            char* sA = sm + (b ^ 1) * 0x8000;  char* sB = sA + 0x4000;
            #pragma unroll
            for (int i = 0; i < 4; i++) {
                uint32_t h0, h1, l0, l1, o = s_sw ^ (i << 3);
                split4(av[i], h0, h1, l0, l1);
                *(uint2*)(sA + o) = make_uint2(h0, h1);
                *(uint2*)(sA + (o ^ 64)) = make_uint2(l0, l1);
                split4(bv[i], h0, h1, l0, l1);
                *(uint2*)(sB + o) = make_uint2(h0, h1);
                *(uint2*)(sB + (o ^ 64)) = make_uint2(l0, l1);
            }
            __syncthreads();
        }
    }

    // epilogue: stage D to smem [128][132], recombine gate/up, split, store act
    __syncthreads();
    float* stg = (float*)sm;
    #pragma unroll
    for (int mt = 0; mt < 2; mt++)
        #pragma unroll
        for (int nt = 0; nt < 8; nt++) {
            int r = wm + mt * 16 + (lane >> 2);
            int c = wn + nt * 8 + (lane & 3) * 2;
            stg[r * 132 + c]           = acc[mt][nt][0];
            stg[r * 132 + c + 1]       = acc[mt][nt][1];
            stg[(r + 8) * 132 + c]     = acc[mt][nt][2];
            stg[(r + 8) * 132 + c + 1] = acc[mt][nt][3];
        }
    __syncthreads();
    const int erow = tid >> 1, ep0 = (tid & 1) * 16;
    const int grow = m0 + erow;
    if (grow < cnt) {
        uint32_t hw[16], lw[16];
        #pragma unroll
        for (int p = 0; p < 16; p++) {
            int pp = ep0 + p;
            float g0 = stg[erow * 132 + 2 * pp],      g1 = stg[erow * 132 + 2 * pp + 1];
            float u0 = stg[erow * 132 + 64 + 2 * pp], u1 = stg[erow * 132 + 65 + 2 * pp];
            float a0 = g0 / (1.f + __expf(-g0)) * u0;
            float a1 = g1 / (1.f + __expf(-g1)) * u1;
            uint32_t hh = packbf(a0, a1);
            hw[p] = hh;
            lw[p] = packbf(a0 - __uint_as_float(hh << 16),
                           a1 - __uint_as_float(hh & 0xFFFF0000u));
        }
        size_t base = ((size_t)e * T + grow) * IW + (n0 >> 1) + ep0;
        #pragma unroll
        for (int q = 0; q < 4; q++) {
            *(uint4*)(g_act_hi + base + 4 * q) = make_uint4(hw[4*q], hw[4*q+1], hw[4*q+2], hw[4*q+3]);
            *(uint4*)(g_act_lo + base + 4 * q) = make_uint4(lw[4*q], lw[4*q+1], lw[4*q+2], lw[4*q+3]);
        }
    }
}

// ---------------- GEMM2: out[tok] += cw * (act @ W2^T) ----------------
// grid (H/128, 4, E); BM=128, BN=128, BK=32; A = pre-split bf16 act.
__global__ void __launch_bounds__(256, 1) k_gemm2(const float* __restrict__ w2,
                                                  float* __restrict__ out) {
    const int e = blockIdx.z, cnt = g_cnt[e];
    const int m0 = blockIdx.y * 128;
    if (m0 >= cnt) return;
    const int n0 = blockIdx.x * 128;

    extern __shared__ char sm[];
    const uint32_t sbase = smem_u32(sm);
    __shared__ int   s_tok[128];
    __shared__ float s_cw [128];

    const int tid = threadIdx.x, lane = tid & 31, wid = tid >> 5;
    if (tid < 128) {
        int r = m0 + tid;
        int rr = (r < cnt) ? r : (cnt - 1);
        s_tok[tid] = g_tok[e][rr];
        s_cw [tid] = (r < cnt) ? g_cw[e][r] : 0.f;
    }
    __syncthreads();

    const int lrow = tid >> 1, half = tid & 1;
    int ar = m0 + lrow; if (ar >= cnt) ar = cnt - 1;
    const uint32_t* ahp = g_act_hi + ((size_t)e * T + ar) * IW + half * 8;
    const uint32_t* alp = g_act_lo + ((size_t)e * T + ar) * IW + half * 8;
    const float* bptr = w2 + ((size_t)e * H + n0 + lrow) * I + half * 16;
    const uint32_t s_sw = (uint32_t)(lrow * 128 + half * 32) ^ (((uint32_t)lrow & 7) << 4);

    const int wm = (wid & 3) * 32, wn = (wid >> 2) * 64;
    const uint32_t a_row = wm + (lane & 15);
    const uint32_t a_swb = (a_row * 128 + ((lane >> 4) << 4)) ^ ((a_row & 7) << 4);
    const uint32_t b_row = wn + (lane & 7) + ((lane >> 4) << 3);
    const uint32_t b_swb = (b_row * 128 + (((lane >> 3) & 1) << 4)) ^ ((b_row & 7) << 4);

    float acc[2][8][4] = {};
    uint4 ah[2], al[2];
    float4 bv[4];
    ah[0] = *(const uint4*)(ahp);      ah[1] = *(const uint4*)(ahp + 4);
    al[0] = *(const uint4*)(alp);      al[1] = *(const uint4*)(alp + 4);
    #pragma unroll
    for (int i = 0; i < 4; i++) bv[i] = *(const float4*)(bptr + 4 * i);
    {   // STS stage 0
        char* sA = sm;  char* sB = sm + 0x4000;
        *(uint4*)(sA + s_sw)             = ah[0];
        *(uint4*)(sA + (s_sw ^ 16))      = ah[1];
        *(uint4*)(sA + (s_sw ^ 64))      = al[0];
        *(uint4*)(sA + (s_sw ^ 64 ^ 16)) = al[1];
        #pragma unroll
        for (int i = 0; i < 4; i++) {
            uint32_t h0, h1, l0, l1, o = s_sw ^ (i << 3);
            split4(bv[i], h0, h1, l0, l1);
            *(uint2*)(sB + o) = make_uint2(h0, h1);
            *(uint2*)(sB + (o ^ 64)) = make_uint2(l0, l1);
        }
    }
    __syncthreads();

    const int KT = I / 32;
    for (int kt = 0; kt < KT; kt++) {
        const int b = kt & 1;
        if (kt + 1 < KT) {
            const int kw = (kt + 1) * 16, k0 = (kt + 1) * 32;
            ah[0] = *(const uint4*)(ahp + kw);      ah[1] = *(const uint4*)(ahp + kw + 4);
            al[0] = *(const uint4*)(alp + kw);      al[1] = *(const uint4*)(alp + kw + 4);
            #pragma unroll
            for (int i = 0; i < 4; i++) bv[i] = *(const float4*)(bptr + k0 + 4 * i);
        }
        const uint32_t aoff = sbase + b * 0x8000;
        const uint32_t boff = aoff + 0x4000;
        COMPUTE_STAGE(aoff, boff);
        if (kt + 1 < KT) {
            __syncthreads();
            char* sA = sm + (b ^ 1) * 0x8000;  char* sB = sA + 0x4000;
            *(uint4*)(sA + s_sw)             = ah[0];
            *(uint4*)(sA + (s_sw ^ 16))      = ah[1];
            *(uint4*)(sA + (s_sw ^ 64))      = al[0];
            *(uint4*)(sA + (s_sw ^ 64 ^ 16)) = al[1];
            #pragma unroll
            for (int i = 0; i < 4; i++) {
                uint32_t h0, h1, l0, l1, o = s_sw ^ (i << 3);
                split4(bv[i], h0, h1, l0, l1);
                *(uint2*)(sB + o) = make_uint2(h0, h1);
                *(uint2*)(sB + (o ^ 64)) = make_uint2(l0, l1);
            }
            __syncthreads();
        }
    }

    // epilogue: scale + atomicAdd (each out element receives exactly 2 adds total)
    #pragma unroll
    for (int mt = 0; mt < 2; mt++)
        #pragma unroll
        for (int nt = 0; nt < 8; nt++) {
            int r = wm + mt * 16 + (lane >> 2);
            int c = n0 + wn + nt * 8 + (lane & 3) * 2;
            if (m0 + r < cnt) {
                float cw = s_cw[r];
                float* op = out + (size_t)s_tok[r] * H + c;
                atomicAdd(op,     acc[mt][nt][0] * cw);
                atomicAdd(op + 1, acc[mt][nt][1] * cw);
            }
            if (m0 + r + 8 < cnt) {
                float cw = s_cw[r + 8];
                float* op = out + (size_t)s_tok[r + 8] * H + c;
                atomicAdd(op,     acc[mt][nt][2] * cw);
                atomicAdd(op + 1, acc[mt][nt][3] * cw);
            }
        }
}

// ---------------- launch ----------------
extern "C" void kernel_launch(void* const* d_in, const int* in_sizes, int n_in,
                              void* d_out, int out_size) {
    const float* x  = (const float*)d_in[0];   // [T, H]
    const float* w1 = (const float*)d_in[1];   // [E, 2I, H]
    const float* w2 = (const float*)d_in[2];   // [E, H, I]
    const float* wg = (const float*)d_in[3];   // [E, H]
    float* out = (float*)d_out;                // [T, 1, H]

    cudaFuncSetAttribute(k_gemm1, cudaFuncAttributeMaxDynamicSharedMemorySize, 128 * 132 * 4);
    cudaFuncSetAttribute(k_gemm2, cudaFuncAttributeMaxDynamicSharedMemorySize, 2 * 0x8000);

    k_reset<<<(T * H + 255) / 256, 256>>>(out);
    k_router<<<T, 256>>>(x, wg);
    k_gemm1<<<dim3(I / 64, 4, E), 256, 128 * 132 * 4>>>(x, w1);
    k_gemm2<<<dim3(H / 128, 4, E), 256, 2 * 0x8000>>>(w2, out);
}